// round 6
// baseline (speedup 1.0000x reference)
#include <cuda_runtime.h>

#define BSEG 16
#define DF   128
#define DC   256
#define THREADS 256
#define GRID (148 * 6)          // 6 CTAs/SM target
#define CHUNK_F_ROWS 128        // 128 * 512B = 64 KB
#define CHUNK_C_ROWS 64         // 64 * 1KB  = 64 KB

// Scratch: __device__ globals (no allocation). Zero-init at load; the last
// block restores everything each call, so every graph replay starts clean.
__device__ float    g_acc_c[BSEG * DC];
__device__ float    g_acc_f[BSEG * DF];
__device__ unsigned g_chunk;
__device__ unsigned g_done;

union U64F2 { unsigned long long u; float2 f; };

__device__ __forceinline__ void fadd2(unsigned long long& acc, unsigned long long v) {
    asm("add.rn.f32x2 %0, %0, %1;" : "+l"(acc) : "l"(v));
}
__device__ __forceinline__ void ld128_cs(const void* p, unsigned long long& x,
                                         unsigned long long& y) {
    asm("ld.global.cs.v2.u64 {%0,%1}, [%2];" : "=l"(x), "=l"(y) : "l"(p));
}

// COLS4 = float4 per row; ROWLANES = THREADS / COLS4 rows per sweep.
template <int COLS4>
__device__ __forceinline__ void reduce_chunk(const float4* __restrict__ feats,
                                             const int* __restrict__ cum,
                                             float* __restrict__ acc,
                                             int row0, int row_end,
                                             float4* __restrict__ sh)
{
    constexpr int ROWLANES = THREADS / COLS4;
    const int tid  = threadIdx.x;
    const int col4 = tid % COLS4;   // consecutive threads -> consecutive 16B (coalesced)
    const int rl   = tid / COLS4;

    int seg = 0;
    while (cum[seg + 1] <= row0) seg++;   // <=16 shared loads

    int row = row0;
    while (row < row_end) {
        const int run_end = min(row_end, cum[seg + 1]);

        unsigned long long a0 = 0, a1 = 0;   // packed f32x2 accumulators
        {
            // zero-init via float packing (0x0 bits == 0.0f pair, fine)
            U64F2 z; z.f = make_float2(0.f, 0.f); a0 = z.u; a1 = z.u;
        }
        #pragma unroll 4
        for (int r = row + rl; r < run_end; r += ROWLANES) {
            unsigned long long x, y;
            ld128_cs(feats + r * COLS4 + col4, x, y);
            fadd2(a0, x);
            fadd2(a1, y);
        }

        // Cross-rowlane reduction in shared, one atomic flush per (chunk, run).
        U64F2 lo, hi; lo.u = a0; hi.u = a1;
        sh[rl * COLS4 + col4] = make_float4(lo.f.x, lo.f.y, hi.f.x, hi.f.y);
        __syncthreads();
        if (rl == 0) {
            float4 s = sh[col4];
            #pragma unroll
            for (int k = 1; k < ROWLANES; k++) {
                float4 v = sh[k * COLS4 + col4];
                s.x += v.x; s.y += v.y; s.z += v.z; s.w += v.w;
            }
            float* dst = acc + seg * (COLS4 * 4) + col4 * 4;
            atomicAdd(dst + 0, s.x);
            atomicAdd(dst + 1, s.y);
            atomicAdd(dst + 2, s.z);
            atomicAdd(dst + 3, s.w);
        }
        __syncthreads();   // protect sh[] before next run / next chunk

        row = run_end;
        seg++;
    }
}

__global__ void __launch_bounds__(THREADS, 6)
fused_segmean_kernel(const float4* __restrict__ feats_f,
                     const float4* __restrict__ feats_c,
                     const int*    __restrict__ lengths_f,
                     const int*    __restrict__ lengths_c,
                     float*        __restrict__ out,
                     int n_f, int n_c)
{
    __shared__ int      cum_f[BSEG + 1];
    __shared__ int      cum_c[BSEG + 1];
    __shared__ float4   sh[THREADS];
    __shared__ unsigned sh_chunk;
    __shared__ bool     is_last;

    const int tid = threadIdx.x;
    if (tid == 0) {
        int c = 0; cum_f[0] = 0;
        #pragma unroll
        for (int b = 0; b < BSEG; b++) { c += lengths_f[b]; cum_f[b + 1] = c; }
    } else if (tid == 32) {
        int c = 0; cum_c[0] = 0;
        #pragma unroll
        for (int b = 0; b < BSEG; b++) { c += lengths_c[b]; cum_c[b + 1] = c; }
    }
    __syncthreads();

    const int chunks_f = (n_f + CHUNK_F_ROWS - 1) / CHUNK_F_ROWS;   // 4096
    const int chunks_c = (n_c + CHUNK_C_ROWS - 1) / CHUNK_C_ROWS;   // 512
    const int total    = chunks_f + chunks_c;

    // ---- dynamic chunk stealing: self-balancing across SMs/waves ----
    for (;;) {
        if (tid == 0) sh_chunk = atomicAdd(&g_chunk, 1u);
        __syncthreads();
        const int c = (int)sh_chunk;
        __syncthreads();                 // all threads read before next overwrite
        if (c >= total) break;

        if (c < chunks_f) {
            int r0 = c * CHUNK_F_ROWS;
            int r1 = min(r0 + CHUNK_F_ROWS, n_f);
            reduce_chunk<DF / 4>(feats_f, cum_f, g_acc_f, r0, r1, sh);
        } else {
            int cc = c - chunks_f;
            int r0 = cc * CHUNK_C_ROWS;
            int r1 = min(r0 + CHUNK_C_ROWS, n_c);
            reduce_chunk<DC / 4>(feats_c, cum_c, g_acc_c, r0, r1, sh);
        }
    }

    // ---- last-block finalize + state restore ----
    __threadfence();
    __syncthreads();
    if (tid == 0) is_last = (atomicAdd(&g_done, 1u) == GRID - 1);
    __syncthreads();
    if (!is_last) return;

    const int DTOT = DC + DF;
    for (int i = tid; i < BSEG * DTOT; i += THREADS) {
        int b = i / DTOT, j = i % DTOT;
        float v, inv;
        if (j < DC) {
            v   = __ldcg(&g_acc_c[b * DC + j]);
            inv = 1.0f / (float)(cum_c[b + 1] - cum_c[b]);
        } else {
            v   = __ldcg(&g_acc_f[b * DF + (j - DC)]);
            inv = 1.0f / (float)(cum_f[b + 1] - cum_f[b]);
        }
        out[i] = v * inv;
    }

    for (int i = tid; i < BSEG * DC; i += THREADS) g_acc_c[i] = 0.f;
    for (int i = tid; i < BSEG * DF; i += THREADS) g_acc_f[i] = 0.f;
    if (tid == 0) { g_done = 0u; g_chunk = 0u; }
}

extern "C" void kernel_launch(void* const* d_in, const int* in_sizes, int n_in,
                              void* d_out, int out_size)
{
    const float4* feats_f   = (const float4*)d_in[0];
    const float4* feats_c   = (const float4*)d_in[1];
    const int*    lengths_f = (const int*)   d_in[2];
    const int*    lengths_c = (const int*)   d_in[3];
    float*        out       = (float*)d_out;

    const int n_f = in_sizes[0] / DF;   // 524288
    const int n_c = in_sizes[1] / DC;   // 32768

    fused_segmean_kernel<<<GRID, THREADS>>>(feats_f, feats_c,
                                            lengths_f, lengths_c,
                                            out, n_f, n_c);
}

// round 7
// speedup vs baseline: 1.0974x; 1.0974x over previous
#include <cuda_runtime.h>

#define BSEG 16
#define DF   128
#define DC   256
#define THREADS 256
#define NBF 2105           // fine blocks:   256 MB / 2105 ≈ 127 KB/block
#define NBC 263            // coarse blocks:  32 MB / 263  ≈ 125 KB/block
#define GRID (NBF + NBC)   // 2368 = 148 SMs * 16 (4 resident, ~4 backfill gens)

// Scratch: __device__ globals (no allocation). Zero-initialized at load;
// the last block re-zeroes them each call, so every call is self-restoring.
__device__ float    g_acc_c[BSEG * DC];
__device__ float    g_acc_f[BSEG * DF];
__device__ unsigned g_done;

// COLS4 = float4 per row (32 for D=128, 64 for D=256); ROWLANES = THREADS/COLS4.
template <int COLS4>
__device__ __forceinline__ void reduce_range(const float4* __restrict__ feats,
                                             const int* __restrict__ cum,
                                             float* __restrict__ acc,
                                             int row0, int row_end,
                                             float4* __restrict__ sh)
{
    constexpr int ROWLANES = THREADS / COLS4;
    const int tid  = threadIdx.x;
    const int col4 = tid % COLS4;   // consecutive threads -> consecutive float4 (coalesced)
    const int rl   = tid / COLS4;

    // Segment containing row0 (<=16 shared loads).
    int seg = 0;
    while (cum[seg + 1] <= row0) seg++;

    int row = row0;
    while (row < row_end) {
        const int run_end = min(row_end, cum[seg + 1]);

        // Long, uninterrupted per-thread register accumulation (deep MLP).
        float4 a = make_float4(0.f, 0.f, 0.f, 0.f);
        #pragma unroll 8
        for (int r = row + rl; r < run_end; r += ROWLANES) {
            float4 v = __ldcs(feats + r * COLS4 + col4);   // streaming, read-once
            a.x += v.x; a.y += v.y; a.z += v.z; a.w += v.w;
        }

        // Cross-rowlane reduction in shared, one atomic flush per (block, run).
        sh[rl * COLS4 + col4] = a;
        __syncthreads();
        if (rl == 0) {
            float4 s = sh[col4];
            #pragma unroll
            for (int k = 1; k < ROWLANES; k++) {
                float4 v = sh[k * COLS4 + col4];
                s.x += v.x; s.y += v.y; s.z += v.z; s.w += v.w;
            }
            float* dst = acc + seg * (COLS4 * 4) + col4 * 4;
            atomicAdd(dst + 0, s.x);
            atomicAdd(dst + 1, s.y);
            atomicAdd(dst + 2, s.z);
            atomicAdd(dst + 3, s.w);
        }
        __syncthreads();   // protect sh[] reuse on the (rare) next run

        row = run_end;
        seg++;
    }
}

__global__ void __launch_bounds__(THREADS, 4)
fused_segmean_kernel(const float4* __restrict__ feats_f,
                     const float4* __restrict__ feats_c,
                     const int*    __restrict__ lengths_f,
                     const int*    __restrict__ lengths_c,
                     float*        __restrict__ out,
                     int n_f, int n_c)
{
    __shared__ int    cum_f[BSEG + 1];
    __shared__ int    cum_c[BSEG + 1];
    __shared__ float4 sh[THREADS];
    __shared__ bool   is_last;

    const int tid = threadIdx.x;
    if (tid == 0) {
        int c = 0; cum_f[0] = 0;
        #pragma unroll
        for (int b = 0; b < BSEG; b++) { c += lengths_f[b]; cum_f[b + 1] = c; }
    } else if (tid == 32) {
        int c = 0; cum_c[0] = 0;
        #pragma unroll
        for (int b = 0; b < BSEG; b++) { c += lengths_c[b]; cum_c[b + 1] = c; }
    }
    __syncthreads();

    // Static, byte-balanced row partition; backfill amortizes finish spread.
    const int bid = blockIdx.x;
    if (bid < NBF) {
        int r0 = (int)((long long)bid       * n_f / NBF);
        int r1 = (int)((long long)(bid + 1) * n_f / NBF);
        if (r0 < r1) reduce_range<DF / 4>(feats_f, cum_f, g_acc_f, r0, r1, sh);
    } else {
        int cb = bid - NBF;
        int r0 = (int)((long long)cb       * n_c / NBC);
        int r1 = (int)((long long)(cb + 1) * n_c / NBC);
        if (r0 < r1) reduce_range<DC / 4>(feats_c, cum_c, g_acc_c, r0, r1, sh);
    }

    // ---- last-block finalize (replaces separate zero + finalize launches) ----
    __threadfence();                      // make this block's atomics L2-visible
    __syncthreads();
    if (tid == 0) is_last = (atomicAdd(&g_done, 1u) == GRID - 1);
    __syncthreads();
    if (!is_last) return;

    const int DTOT = DC + DF;
    for (int i = tid; i < BSEG * DTOT; i += THREADS) {
        int b = i / DTOT, j = i % DTOT;
        float v, inv;
        if (j < DC) {
            v   = __ldcg(&g_acc_c[b * DC + j]);
            inv = 1.0f / (float)(cum_c[b + 1] - cum_c[b]);
        } else {
            v   = __ldcg(&g_acc_f[b * DF + (j - DC)]);
            inv = 1.0f / (float)(cum_f[b + 1] - cum_f[b]);
        }
        out[i] = v * inv;
    }

    // Restore state for the next graph replay.
    for (int i = tid; i < BSEG * DC; i += THREADS) g_acc_c[i] = 0.f;
    for (int i = tid; i < BSEG * DF; i += THREADS) g_acc_f[i] = 0.f;
    if (tid == 0) g_done = 0u;
}

extern "C" void kernel_launch(void* const* d_in, const int* in_sizes, int n_in,
                              void* d_out, int out_size)
{
    const float4* feats_f   = (const float4*)d_in[0];
    const float4* feats_c   = (const float4*)d_in[1];
    const int*    lengths_f = (const int*)   d_in[2];
    const int*    lengths_c = (const int*)   d_in[3];
    float*        out       = (float*)d_out;

    const int n_f = in_sizes[0] / DF;   // 524288
    const int n_c = in_sizes[1] / DC;   // 32768

    fused_segmean_kernel<<<GRID, THREADS>>>(feats_f, feats_c,
                                            lengths_f, lengths_c,
                                            out, n_f, n_c);
}

// round 12
// speedup vs baseline: 1.2698x; 1.1571x over previous
#include <cuda_runtime.h>

#define BSEG 16
#define DF   128
#define DC   256
#define THREADS 256
#define NBF 789            // fine blocks:   256 MB / 789 ≈ 340 KB/block
#define NBC 99             // coarse blocks:  32 MB / 99  ≈ 339 KB/block
#define GRID (NBF + NBC)   // 888 = 148 SMs * 6 CTAs -> exactly one wave

// Scratch: __device__ globals (no allocation). Zero-initialized at load;
// the last block re-zeroes them each call, so every call is self-restoring.
__device__ float    g_acc_c[BSEG * DC];
__device__ float    g_acc_f[BSEG * DF];
__device__ unsigned g_done;

// COLS4 = float4 per row (32 for D=128, 64 for D=256); ROWLANES = THREADS/COLS4.
template <int COLS4>
__device__ __forceinline__ void reduce_range(const float4* __restrict__ feats,
                                             const int* __restrict__ cum,
                                             float* __restrict__ acc,
                                             int row0, int row_end,
                                             float4* __restrict__ sh)
{
    constexpr int ROWLANES = THREADS / COLS4;
    const int tid  = threadIdx.x;
    const int col4 = tid % COLS4;   // consecutive threads -> consecutive float4 (coalesced)
    const int rl   = tid / COLS4;

    // Segment containing row0 (<=16 shared loads).
    int seg = 0;
    while (cum[seg + 1] <= row0) seg++;

    int row = row0;
    while (row < row_end) {
        const int run_end = min(row_end, cum[seg + 1]);

        // Long uninterrupted stream; two independent accumulator chains so at
        // least 2 loads are always in flight per thread even at 40 regs.
        float4 a0 = make_float4(0.f, 0.f, 0.f, 0.f);
        float4 a1 = make_float4(0.f, 0.f, 0.f, 0.f);
        int r = row + rl;
        #pragma unroll 4
        for (; r + ROWLANES < run_end; r += 2 * ROWLANES) {
            float4 v0 = __ldcs(feats + (r)            * COLS4 + col4);
            float4 v1 = __ldcs(feats + (r + ROWLANES) * COLS4 + col4);
            a0.x += v0.x; a0.y += v0.y; a0.z += v0.z; a0.w += v0.w;
            a1.x += v1.x; a1.y += v1.y; a1.z += v1.z; a1.w += v1.w;
        }
        if (r < run_end) {
            float4 v = __ldcs(feats + r * COLS4 + col4);
            a0.x += v.x; a0.y += v.y; a0.z += v.z; a0.w += v.w;
        }
        a0.x += a1.x; a0.y += a1.y; a0.z += a1.z; a0.w += a1.w;

        // Cross-rowlane reduction in shared, one atomic flush per (block, run).
        sh[rl * COLS4 + col4] = a0;
        __syncthreads();
        if (rl == 0) {
            float4 s = sh[col4];
            #pragma unroll
            for (int k = 1; k < ROWLANES; k++) {
                float4 v = sh[k * COLS4 + col4];
                s.x += v.x; s.y += v.y; s.z += v.z; s.w += v.w;
            }
            float* dst = acc + seg * (COLS4 * 4) + col4 * 4;
            atomicAdd(dst + 0, s.x);
            atomicAdd(dst + 1, s.y);
            atomicAdd(dst + 2, s.z);
            atomicAdd(dst + 3, s.w);
        }
        __syncthreads();   // protect sh[] reuse on the (rare) next run

        row = run_end;
        seg++;
    }
}

__global__ void __launch_bounds__(THREADS, 6)
fused_segmean_kernel(const float4* __restrict__ feats_f,
                     const float4* __restrict__ feats_c,
                     const int*    __restrict__ lengths_f,
                     const int*    __restrict__ lengths_c,
                     float*        __restrict__ out,
                     int n_f, int n_c)
{
    __shared__ int    cum_f[BSEG + 1];
    __shared__ int    cum_c[BSEG + 1];
    __shared__ float4 sh[THREADS];
    __shared__ bool   is_last;

    const int tid = threadIdx.x;
    if (tid == 0) {
        int c = 0; cum_f[0] = 0;
        #pragma unroll
        for (int b = 0; b < BSEG; b++) { c += lengths_f[b]; cum_f[b + 1] = c; }
    } else if (tid == 32) {
        int c = 0; cum_c[0] = 0;
        #pragma unroll
        for (int b = 0; b < BSEG; b++) { c += lengths_c[b]; cum_c[b + 1] = c; }
    }
    __syncthreads();

    // Static, byte-balanced row partition; one full wave, long streams.
    const int bid = blockIdx.x;
    if (bid < NBF) {
        int r0 = (int)((long long)bid       * n_f / NBF);
        int r1 = (int)((long long)(bid + 1) * n_f / NBF);
        if (r0 < r1) reduce_range<DF / 4>(feats_f, cum_f, g_acc_f, r0, r1, sh);
    } else {
        int cb = bid - NBF;
        int r0 = (int)((long long)cb       * n_c / NBC);
        int r1 = (int)((long long)(cb + 1) * n_c / NBC);
        if (r0 < r1) reduce_range<DC / 4>(feats_c, cum_c, g_acc_c, r0, r1, sh);
    }

    // ---- last-block finalize (replaces separate zero + finalize launches) ----
    __threadfence();                      // make this block's atomics L2-visible
    __syncthreads();
    if (tid == 0) is_last = (atomicAdd(&g_done, 1u) == GRID - 1);
    __syncthreads();
    if (!is_last) return;

    const int DTOT = DC + DF;
    for (int i = tid; i < BSEG * DTOT; i += THREADS) {
        int b = i / DTOT, j = i % DTOT;
        float v, inv;
        if (j < DC) {
            v   = __ldcg(&g_acc_c[b * DC + j]);
            inv = 1.0f / (float)(cum_c[b + 1] - cum_c[b]);
        } else {
            v   = __ldcg(&g_acc_f[b * DF + (j - DC)]);
            inv = 1.0f / (float)(cum_f[b + 1] - cum_f[b]);
        }
        out[i] = v * inv;
    }

    // Restore state for the next graph replay.
    for (int i = tid; i < BSEG * DC; i += THREADS) g_acc_c[i] = 0.f;
    for (int i = tid; i < BSEG * DF; i += THREADS) g_acc_f[i] = 0.f;
    if (tid == 0) g_done = 0u;
}

extern "C" void kernel_launch(void* const* d_in, const int* in_sizes, int n_in,
                              void* d_out, int out_size)
{
    const float4* feats_f   = (const float4*)d_in[0];
    const float4* feats_c   = (const float4*)d_in[1];
    const int*    lengths_f = (const int*)   d_in[2];
    const int*    lengths_c = (const int*)   d_in[3];
    float*        out       = (float*)d_out;

    const int n_f = in_sizes[0] / DF;   // 524288
    const int n_c = in_sizes[1] / DC;   // 32768

    fused_segmean_kernel<<<GRID, THREADS>>>(feats_f, feats_c,
                                            lengths_f, lengths_c,
                                            out, n_f, n_c);
}